// round 1
// baseline (speedup 1.0000x reference)
#include <cuda_runtime.h>

#define TSEQ  512
#define BATCH 128
#define HID   1024
#define NLAY  4
#define BH    (BATCH*HID)

#define MR 64      // M tile (batch rows)
#define NR 64      // N tile (output cols)
#define KB 32      // K chunk
#define LROW 36    // padded smem row (floats): lane stride 144B == 16 mod 128 -> conflict-free LDS.128

// Ring buffers for hidden state of layers 0..2 (layer 3 lives in d_out). 3 MB.
__device__ float g_hbuf[3*2*BH];

// Packed dual-FMA: the sm_103a FFMA2 (2x FFMA throughput), only reachable via PTX.
__device__ __forceinline__ void fma2(unsigned long long& c,
                                     unsigned long long a,
                                     unsigned long long b) {
    asm("fma.rn.f32x2 %0, %1, %2, %0;" : "+l"(c) : "l"(a), "l"(b));
}

// One wavefront step s: computes h[i][t] for all valid (i, t) with t + i == s.
// h[i][t] = tanh( cur @ Wih[i]^T + hprev @ Whh[i]^T + bih[i] + bhh[i] )
// fused as a single [128,2048] @ [2048,1024]^T GEMM (concat along K).
__global__ void __launch_bounds__(256, 1)
rnn_wave(int s,
         const float* __restrict__ x,
         const float* __restrict__ Wih,
         const float* __restrict__ Whh,
         const float* __restrict__ bih,
         const float* __restrict__ bhh,
         float* __restrict__ out)
{
    const int layer = blockIdx.y;
    const int t = s - layer;
    if (t < 0 || t >= TSEQ) return;

    const int mt = blockIdx.x >> 4;   // 0..1
    const int nt = blockIdx.x & 15;   // 0..15
    const int m0 = mt * MR;
    const int n0 = nt * NR;

    const float* cur = (layer == 0)
        ? (x + (size_t)t * BH)
        : (g_hbuf + (size_t)((layer-1)*2 + (t & 1)) * BH);
    const float* hprev = (t == 0) ? (const float*)0
        : (layer == NLAY-1) ? (out + (size_t)(t-1) * BH)
                            : (g_hbuf + (size_t)(layer*2 + ((t-1) & 1)) * BH);
    float* dst = (layer == NLAY-1)
        ? (out + (size_t)t * BH)
        : (g_hbuf + (size_t)(layer*2 + (t & 1)) * BH);

    const float* Wi = Wih + (size_t)layer * HID * HID;
    const float* Wh = Whh + (size_t)layer * HID * HID;

    __shared__ __align__(16) float As[2][MR*LROW];
    __shared__ __align__(16) float Ws[2][NR*LROW];

    const int tid = threadIdx.x;
    const int tx  = tid & 15;   // n group
    const int ty  = tid >> 4;   // m group (0..15)

    // t==0: h_prev is zero -> skip the second half of K entirely.
    const int nChunks = (t == 0) ? (HID / KB) : (2 * HID / KB);

    unsigned long long acc[4][4];
    #pragma unroll
    for (int mi = 0; mi < 4; mi++)
        #pragma unroll
        for (int ni = 0; ni < 4; ni++) acc[mi][ni] = 0ull;

    float4 pa[2], pw[2];

    auto ldg_chunk = [&](int c) {
        const int k0 = c * KB;
        const float* asrc; const float* wsrc; int koff;
        if (k0 < HID) { asrc = cur;   wsrc = Wi; koff = k0; }
        else          { asrc = hprev; wsrc = Wh; koff = k0 - HID; }
        #pragma unroll
        for (int j = 0; j < 2; j++) {
            const int l = tid + 256*j;        // 512 float4s per 64x32 tile
            const int row = l >> 3;           // 0..63
            const int kq  = l & 7;            // 0..7
            pa[j] = *reinterpret_cast<const float4*>(asrc + (size_t)(m0+row)*HID + koff + kq*4);
            pw[j] = *reinterpret_cast<const float4*>(wsrc + (size_t)(n0+row)*HID + koff + kq*4);
        }
    };

    auto sts_chunk = [&](int buf) {
        #pragma unroll
        for (int j = 0; j < 2; j++) {
            const int l = tid + 256*j;
            const int row = l >> 3;
            const int kq  = l & 7;
            *reinterpret_cast<float4*>(&As[buf][row*LROW + kq*4]) = pa[j];
            *reinterpret_cast<float4*>(&Ws[buf][row*LROW + kq*4]) = pw[j];
        }
    };

    auto compute_chunk = [&](int buf) {
        #pragma unroll
        for (int kk = 0; kk < KB; kk += 4) {
            unsigned long long af[2][4], wf[2][4];
            #pragma unroll
            for (int mi = 0; mi < 4; mi++) {
                double2 v = *reinterpret_cast<const double2*>(&As[buf][(mi*16+ty)*LROW + kk]);
                af[0][mi] = __double_as_longlong(v.x);   // (a[k], a[k+1])
                af[1][mi] = __double_as_longlong(v.y);   // (a[k+2], a[k+3])
            }
            #pragma unroll
            for (int ni = 0; ni < 4; ni++) {
                double2 v = *reinterpret_cast<const double2*>(&Ws[buf][(ni*16+tx)*LROW + kk]);
                wf[0][ni] = __double_as_longlong(v.x);
                wf[1][ni] = __double_as_longlong(v.y);
            }
            // Two passes: 16 independent FMA2s between reuses of each acc (hides lat=4).
            #pragma unroll
            for (int p = 0; p < 2; p++)
                #pragma unroll
                for (int mi = 0; mi < 4; mi++)
                    #pragma unroll
                    for (int ni = 0; ni < 4; ni++)
                        fma2(acc[mi][ni], af[p][mi], wf[p][ni]);
        }
    };

    ldg_chunk(0);
    sts_chunk(0);
    __syncthreads();

    for (int c = 0; c < nChunks; c++) {
        if (c + 1 < nChunks) ldg_chunk(c + 1);
        compute_chunk(c & 1);
        if (c + 1 < nChunks) sts_chunk((c + 1) & 1);
        __syncthreads();
    }

    // Epilogue: fold even/odd-K halves, add biases, tanh, store.
    #pragma unroll
    for (int ni = 0; ni < 4; ni++) {
        const int n = n0 + ni*16 + tx;
        const float bsum = bih[layer*HID + n] + bhh[layer*HID + n];
        #pragma unroll
        for (int mi = 0; mi < 4; mi++) {
            const int m = m0 + mi*16 + ty;
            const unsigned long long a = acc[mi][ni];
            const float lo = __uint_as_float((unsigned)a);
            const float hi = __uint_as_float((unsigned)(a >> 32));
            dst[(size_t)m*HID + n] = tanhf(lo + hi + bsum);
        }
    }
}

extern "C" void kernel_launch(void* const* d_in, const int* in_sizes, int n_in,
                              void* d_out, int out_size) {
    const float* x   = (const float*)d_in[0];
    const float* Wih = (const float*)d_in[1];
    const float* Whh = (const float*)d_in[2];
    const float* bih = (const float*)d_in[3];
    const float* bhh = (const float*)d_in[4];
    float* out = (float*)d_out;

    // Wavefront s = t + layer: 512 + 4 - 1 = 515 sequential launches.
    // Kernel boundaries provide all cross-(t,layer) synchronization.
    const dim3 grid(32, NLAY);
    for (int s = 0; s < TSEQ + NLAY - 1; s++) {
        rnn_wave<<<grid, 256>>>(s, x, Wih, Whh, bih, bhh, out);
    }
}

// round 2
// speedup vs baseline: 1.0278x; 1.0278x over previous
#include <cuda_runtime.h>

#define TSEQ  512
#define BATCH 128
#define HID   1024
#define NLAY  4
#define BH    (BATCH*HID)

#define MR 64      // M tile (batch rows)
#define NR 64      // N tile (output cols)
#define KB 32      // K chunk
#define LROW 36    // padded smem row (floats): 144B stride -> conflict-free LDS.128 in 8-lane phases

// Ring buffers for hidden state of layers 0..2 (layer 3 lives in d_out). 3 MB.
__device__ float g_hbuf[3*2*BH];

// Packed dual-FMA: sm_103a FFMA2 (2x FFMA throughput), only reachable via PTX.
__device__ __forceinline__ void fma2(unsigned long long& c,
                                     unsigned long long a,
                                     unsigned long long b) {
    asm("fma.rn.f32x2 %0, %1, %2, %0;" : "+l"(c) : "l"(a), "l"(b));
}

__device__ __forceinline__ void cp_async16(unsigned smem_addr, const void* gptr) {
    asm volatile("cp.async.ca.shared.global [%0], [%1], 16;\n"
                 :: "r"(smem_addr), "l"(gptr));
}
__device__ __forceinline__ void cp_commit() {
    asm volatile("cp.async.commit_group;\n" ::: "memory");
}
template<int N>
__device__ __forceinline__ void cp_wait() {
    asm volatile("cp.async.wait_group %0;\n" :: "n"(N) : "memory");
}

// One wavefront step s: h[i][t] for all (i,t) with t+i == s.
// h[i][t] = tanh( cur @ Wih[i]^T + hprev @ Whh[i]^T + bih[i] + bhh[i] )
// fused as [128,2048] @ [2048,1024]^T (K-concat).
__global__ void __launch_bounds__(512)
rnn_wave(int s,
         const float* __restrict__ x,
         const float* __restrict__ Wih,
         const float* __restrict__ Whh,
         const float* __restrict__ bih,
         const float* __restrict__ bhh,
         float* __restrict__ out)
{
    const int layer = blockIdx.y;
    const int t = s - layer;
    if (t < 0 || t >= TSEQ) return;

    const int mt = blockIdx.x >> 4;   // 0..1
    const int nt = blockIdx.x & 15;   // 0..15
    const int m0 = mt * MR;
    const int n0 = nt * NR;

    const float* cur = (layer == 0)
        ? (x + (size_t)t * BH)
        : (g_hbuf + (size_t)((layer-1)*2 + (t & 1)) * BH);
    const float* hprev = (t == 0) ? (const float*)0
        : (layer == NLAY-1) ? (out + (size_t)(t-1) * BH)
                            : (g_hbuf + (size_t)(layer*2 + ((t-1) & 1)) * BH);
    float* dst = (layer == NLAY-1)
        ? (out + (size_t)t * BH)
        : (g_hbuf + (size_t)(layer*2 + (t & 1)) * BH);

    const float* Wi = Wih + (size_t)layer * HID * HID;
    const float* Wh = Whh + (size_t)layer * HID * HID;

    __shared__ __align__(16) float As[2][MR*LROW];
    __shared__ __align__(16) float Ws[2][NR*LROW];

    const int tid = threadIdx.x;
    const int txn = tid & 31;   // n lane (0..31)
    const int ty  = tid >> 5;   // m warp group (0..15)

    // Per-thread load slot: one float4 of A and one of W per chunk.
    const int lrow = tid >> 3;  // 0..63
    const int lkq  = tid & 7;   // 0..7

    const unsigned sAs0 = (unsigned)__cvta_generic_to_shared(&As[0][lrow*LROW + lkq*4]);
    const unsigned sAs1 = (unsigned)__cvta_generic_to_shared(&As[1][lrow*LROW + lkq*4]);
    const unsigned sWs0 = (unsigned)__cvta_generic_to_shared(&Ws[0][lrow*LROW + lkq*4]);
    const unsigned sWs1 = (unsigned)__cvta_generic_to_shared(&Ws[1][lrow*LROW + lkq*4]);

    // t==0: h_prev is zero -> only the first HID of K.
    const int nChunks = (t == 0) ? (HID / KB) : (2 * HID / KB);

    unsigned long long acc[4][2];
    #pragma unroll
    for (int mi = 0; mi < 4; mi++) { acc[mi][0] = 0ull; acc[mi][1] = 0ull; }

    auto issue_chunk = [&](int c, int buf) {
        const int k0 = c * KB;
        const float* asrc; const float* wsrc; int koff;
        if (k0 < HID) { asrc = cur;   wsrc = Wi; koff = k0; }
        else          { asrc = hprev; wsrc = Wh; koff = k0 - HID; }
        cp_async16(buf ? sAs1 : sAs0, asrc + (size_t)(m0+lrow)*HID + koff + lkq*4);
        cp_async16(buf ? sWs1 : sWs0, wsrc + (size_t)(n0+lrow)*HID + koff + lkq*4);
        cp_commit();
    };

    auto compute_chunk = [&](int buf) {
        #pragma unroll
        for (int kk = 0; kk < KB; kk += 4) {
            unsigned long long af[2][4], wf[2][2];
            #pragma unroll
            for (int mi = 0; mi < 4; mi++) {
                double2 v = *reinterpret_cast<const double2*>(&As[buf][(mi*16+ty)*LROW + kk]);
                af[0][mi] = __double_as_longlong(v.x);   // (a[k],   a[k+1])
                af[1][mi] = __double_as_longlong(v.y);   // (a[k+2], a[k+3])
            }
            #pragma unroll
            for (int ni = 0; ni < 2; ni++) {
                double2 v = *reinterpret_cast<const double2*>(&Ws[buf][(ni*32+txn)*LROW + kk]);
                wf[0][ni] = __double_as_longlong(v.x);
                wf[1][ni] = __double_as_longlong(v.y);
            }
            // 8 independent FMA2s between acc reuses (covers lat=4).
            #pragma unroll
            for (int p = 0; p < 2; p++)
                #pragma unroll
                for (int mi = 0; mi < 4; mi++)
                    #pragma unroll
                    for (int ni = 0; ni < 2; ni++)
                        fma2(acc[mi][ni], af[p][mi], wf[p][ni]);
        }
    };

    issue_chunk(0, 0);

    for (int c = 0; c < nChunks; c++) {
        if (c + 1 < nChunks) {
            issue_chunk(c + 1, (c + 1) & 1);
            cp_wait<1>();
        } else {
            cp_wait<0>();
        }
        __syncthreads();          // chunk c visible to all warps
        compute_chunk(c & 1);
        __syncthreads();          // all reads of buf (c&1) done before chunk c+2 overwrites it
    }

    // Epilogue: fold even/odd-K halves, add biases, tanh, store.
    #pragma unroll
    for (int ni = 0; ni < 2; ni++) {
        const int n = n0 + ni*32 + txn;
        const float bsum = bih[layer*HID + n] + bhh[layer*HID + n];
        #pragma unroll
        for (int mi = 0; mi < 4; mi++) {
            const int m = m0 + mi*16 + ty;
            const unsigned long long a = acc[mi][ni];
            const float lo = __uint_as_float((unsigned)a);
            const float hi = __uint_as_float((unsigned)(a >> 32));
            dst[(size_t)m*HID + n] = tanhf(lo + hi + bsum);
        }
    }
}

extern "C" void kernel_launch(void* const* d_in, const int* in_sizes, int n_in,
                              void* d_out, int out_size) {
    const float* x   = (const float*)d_in[0];
    const float* Wih = (const float*)d_in[1];
    const float* Whh = (const float*)d_in[2];
    const float* bih = (const float*)d_in[3];
    const float* bhh = (const float*)d_in[4];
    float* out = (float*)d_out;

    // Wavefront s = t + layer: 515 sequential launches; kernel boundaries = sync.
    const dim3 grid(32, NLAY);
    for (int s = 0; s < TSEQ + NLAY - 1; s++) {
        rnn_wave<<<grid, 512>>>(s, x, Wih, Whh, bih, bhh, out);
    }
}